// round 3
// baseline (speedup 1.0000x reference)
#include <cuda_runtime.h>

#define Nn 64
#define Tt 512
#define Vv 25
#define CINn 3
#define CHh 64
#define FFf 25
#define G4 100   // 4*F

// scratch: attention coefficients (N,T,V,V) = 20.48M floats = 82MB
__device__ float g_coefs[(long long)Nn * Tt * Vv * Vv];

__device__ __forceinline__ float hsig(float x) { return __saturatef(fmaf(0.2f, x, 0.5f)); }

__device__ __forceinline__ unsigned long long pk2(float a, float b) {
    unsigned long long r;
    asm("mov.b64 %0, {%1,%2};" : "=l"(r) : "f"(a), "f"(b));
    return r;
}
__device__ __forceinline__ void upk2(unsigned long long v, float& a, float& b) {
    asm("mov.b64 {%0,%1}, %2;" : "=f"(a), "=f"(b) : "l"(v));
}
__device__ __forceinline__ unsigned long long ffma2(
    unsigned long long a, unsigned long long b, unsigned long long c) {
    unsigned long long d;
    asm("fma.rn.f32x2 %0, %1, %2, %3;" : "=l"(d) : "l"(a), "l"(b), "l"(c));
    return d;
}

// One block per (n,v) lane: full T=512 LSTM scan with fused 1x1-conv input,
// fused input projection (f32x2-packed), and fused softmax of h.
__global__ __launch_bounds__(128) void scan_kernel(
    const float* __restrict__ x,     // (N,T,V,3)
    const float* __restrict__ Wc,    // (3,64)
    const float* __restrict__ bc,    // (64)
    const float* __restrict__ Wl,    // (64,100)
    const float* __restrict__ Ul,    // (25,100)
    const float* __restrict__ bl,    // (100)
    const float* __restrict__ bias)  // (25,25)
{
    const int blk = blockIdx.x;           // n*25 + v
    const int n = blk / Vv, v = blk % Vv;
    const int tid = threadIdx.x;

    __shared__ __align__(16) float x1s[CHh];
    __shared__ __align__(16) float hs[28];   // padded; [25..27] stay 0
    __shared__ float zs[G4];

    // gate-column weights, pair-packed along the contraction dim (tid < 100)
    unsigned long long Wp[CHh / 2];          // 32 x f32x2  (64 regs)
    unsigned long long Up[13];               // covers h[0..25], h[25]-pad weight 0
    float bg = 0.f;
    if (tid < G4) {
#pragma unroll
        for (int i = 0; i < CHh / 2; i++)
            Wp[i] = pk2(Wl[(2 * i) * G4 + tid], Wl[(2 * i + 1) * G4 + tid]);
#pragma unroll
        for (int i = 0; i < 12; i++)
            Up[i] = pk2(Ul[(2 * i) * G4 + tid], Ul[(2 * i + 1) * G4 + tid]);
        Up[12] = pk2(Ul[24 * G4 + tid], 0.f);
        bg = bl[tid];
    }
    float wc0 = 0.f, wc1 = 0.f, wc2 = 0.f, bcv = 0.f;
    if (tid < CHh) {
        wc0 = Wc[0 * CHh + tid];
        wc1 = Wc[1 * CHh + tid];
        wc2 = Wc[2 * CHh + tid];
        bcv = bc[tid];
    }
    float biasv = 0.f;
    if (tid < Vv) biasv = bias[v * Vv + tid];

    float cst = 0.f;                 // cell state (tid < 25)
    if (tid < 28) hs[tid] = 0.f;
    __syncthreads();

    const float* xrow = x + ((long long)n * Tt * Vv + v) * CINn;
    float* cof = g_coefs + ((long long)n * Tt * Vv + v) * Vv;

    for (int t = 0; t < Tt; t++) {
        // ---- phase 1: x1 row (64 channels) from 1x1 conv ----
        if (tid < CHh) {
            const float* xp = xrow + (long long)t * Vv * CINn;
            float a = fmaf(xp[0], wc0, bcv);
            a = fmaf(xp[1], wc1, a);
            a = fmaf(xp[2], wc2, a);
            x1s[tid] = fmaxf(a, 0.f);
        }
        __syncthreads();  // x1s ready; also orders previous step's hs writes

        // ---- phase 2: gate pre-activations z[g], f32x2 packed ----
        if (tid < G4) {
            unsigned long long acc2 = pk2(bg, 0.f);
            const unsigned long long* x2 = (const unsigned long long*)x1s;
#pragma unroll
            for (int i = 0; i < CHh / 2; i++)
                acc2 = ffma2(x2[i], Wp[i], acc2);
            const unsigned long long* h2 = (const unsigned long long*)hs;
#pragma unroll
            for (int i = 0; i < 13; i++)
                acc2 = ffma2(h2[i], Up[i], acc2);
            float alo, ahi;
            upk2(acc2, alo, ahi);
            zs[tid] = alo + ahi;
        }
        __syncthreads();  // zs ready

        // ---- phase 3: gates, state update, fused softmax (warp 0) ----
        if (tid < 32) {
            float a = -1e30f;
            if (tid < FFf) {
                float zi = zs[tid];
                float zf = zs[tid + 25];
                float zg = zs[tid + 50];
                float zo = zs[tid + 75];
                cst = hsig(zf) * cst + hsig(zi) * tanhf(zg);
                float h = hsig(zo) * tanhf(cst);
                hs[tid] = h;
                a = (h > 0.f ? h : 0.2f * h) + biasv;   // leaky_relu(0.2) + bias
            }
            float m = a;
#pragma unroll
            for (int off = 16; off >= 1; off >>= 1)
                m = fmaxf(m, __shfl_xor_sync(0xffffffffu, m, off));
            float e = (tid < FFf) ? __expf(a - m) : 0.f;
            float s = e;
#pragma unroll
            for (int off = 16; off >= 1; off >>= 1)
                s += __shfl_xor_sync(0xffffffffu, s, off);
            if (tid < FFf) cof[(long long)t * Vv * Vv + tid] = e / s;
        }
        // no extra sync: next iteration's first __syncthreads orders hs/zs
    }
}

// One block per (n,t): recompute x1 tile (25x64), load coefs (25x25),
// produce out = coefs @ x1 (25x64), float4 stores.
__global__ __launch_bounds__(256) void agg_kernel(
    const float* __restrict__ x,
    const float* __restrict__ Wc,
    const float* __restrict__ bc,
    float* __restrict__ out)
{
    const int nt = blockIdx.x;
    const int tid = threadIdx.x;

    __shared__ __align__(16) float x1s[Vv][CHh];   // 6.4KB
    __shared__ float cofs[Vv][Vv];                 // 2.5KB
    __shared__ float xs[Vv * CINn];                // 75 floats

    const float* xblk = x + (long long)nt * Vv * CINn;
    if (tid < Vv * CINn) xs[tid] = xblk[tid];
    const float* cblk = g_coefs + (long long)nt * Vv * Vv;
    for (int i = tid; i < Vv * Vv; i += 256) cofs[i / Vv][i % Vv] = cblk[i];
    __syncthreads();

    for (int i = tid; i < Vv * CHh; i += 256) {
        int w = i >> 6, d = i & 63;
        float a = fmaf(xs[w * 3 + 0], Wc[0 * CHh + d], bc[d]);
        a = fmaf(xs[w * 3 + 1], Wc[1 * CHh + d], a);
        a = fmaf(xs[w * 3 + 2], Wc[2 * CHh + d], a);
        x1s[w][d] = fmaxf(a, 0.f);
    }
    __syncthreads();

    float4* oblk = (float4*)(out + (long long)nt * Vv * CHh);
    for (int i = tid; i < Vv * 16; i += 256) {   // 400 float4 outputs
        int v = i >> 4, d4 = i & 15;
        float4 acc = make_float4(0.f, 0.f, 0.f, 0.f);
#pragma unroll
        for (int w = 0; w < Vv; w++) {
            float cf = cofs[v][w];
            float4 xv = ((const float4*)x1s[w])[d4];
            acc.x = fmaf(cf, xv.x, acc.x);
            acc.y = fmaf(cf, xv.y, acc.y);
            acc.z = fmaf(cf, xv.z, acc.z);
            acc.w = fmaf(cf, xv.w, acc.w);
        }
        oblk[i] = acc;
    }
}

extern "C" void kernel_launch(void* const* d_in, const int* in_sizes, int n_in,
                              void* d_out, int out_size)
{
    const float* x    = (const float*)d_in[0];
    const float* Wc   = (const float*)d_in[1];
    const float* bc   = (const float*)d_in[2];
    const float* Wl   = (const float*)d_in[3];
    const float* Ul   = (const float*)d_in[4];
    const float* bl   = (const float*)d_in[5];
    const float* bias = (const float*)d_in[6];
    float* out = (float*)d_out;

    scan_kernel<<<Nn * Vv, 128>>>(x, Wc, bc, Wl, Ul, bl, bias);
    agg_kernel<<<Nn * Tt, 256>>>(x, Wc, bc, out);
}

// round 13
// speedup vs baseline: 1.2283x; 1.2283x over previous
#include <cuda_runtime.h>

#define Nn 64
#define Tt 512
#define Vv 25
#define CINn 3
#define CHh 64
#define FFf 25
#define G4 100   // 4*F
#define XST 75   // Vv*CINn

// scratch: raw LSTM hidden states (N,T,V,F) = 20.48M floats = 82MB
__device__ float g_h[(long long)Nn * Tt * Vv * FFf];

__device__ __forceinline__ float hsig(float x) { return __saturatef(fmaf(0.2f, x, 0.5f)); }
// accurate tanh: exact identity via MUFU exp + fast div (~1e-7 abs err)
__device__ __forceinline__ float tanh_acc(float x) {
    float t = __expf(2.0f * x);
    return 1.0f - __fdividef(2.0f, t + 1.0f);
}
__device__ __forceinline__ unsigned long long pk2(float a, float b) {
    unsigned long long r; asm("mov.b64 %0, {%1,%2};" : "=l"(r) : "f"(a), "f"(b)); return r;
}
__device__ __forceinline__ void upk2(unsigned long long v, float& a, float& b) {
    asm("mov.b64 {%0,%1}, %2;" : "=f"(a), "=f"(b) : "l"(v));
}
__device__ __forceinline__ unsigned long long ffma2(
    unsigned long long a, unsigned long long b, unsigned long long c) {
    unsigned long long d;
    asm("fma.rn.f32x2 %0, %1, %2, %3;" : "=l"(d) : "l"(a), "l"(b), "l"(c));
    return d;
}
__device__ __forceinline__ unsigned long long add2(
    unsigned long long a, unsigned long long b) {
    unsigned long long d;
    asm("add.rn.f32x2 %0, %1, %2;" : "=l"(d) : "l"(a), "l"(b));
    return d;
}

// One block per (n,v) lane, 128 threads. R3-verified phase structure:
//   phase1: tid<64 conv -> x1s      (sync)
//   phase2: tid<100 gate column tid -> zs   (sync)
//   phase3: tid<25 state update, store h
__global__ __launch_bounds__(128) void scan_kernel(
    const float* __restrict__ x,     // (N,T,V,3)
    const float* __restrict__ Wc,    // (3,64)
    const float* __restrict__ bc,    // (64)
    const float* __restrict__ Wl,    // (64,100)
    const float* __restrict__ Ul,    // (25,100)
    const float* __restrict__ bl)    // (100)
{
    const int blk = blockIdx.x;           // n*25 + v
    const int n = blk / Vv, v = blk % Vv;
    const int tid = threadIdx.x;

    __shared__ __align__(16) float xsm[Tt * CINn];   // 6KB raw x for this lane
    __shared__ __align__(16) float x1s[CHh];
    __shared__ __align__(16) float hs[28];           // [25..27] stay 0
    __shared__ float zs[G4];

    // ---- preload x time-series for this lane ----
    {
        const float* xrow = x + ((long long)n * Tt * Vv + v) * CINn;
        for (int t = tid; t < Tt; t += 128) {
            xsm[t * 3 + 0] = xrow[(long long)t * XST + 0];
            xsm[t * 3 + 1] = xrow[(long long)t * XST + 1];
            xsm[t * 3 + 2] = xrow[(long long)t * XST + 2];
        }
    }

    // ---- gate-column weights (column = tid), pair-packed ----
    unsigned long long Wp[CHh / 2];   // 32 pairs over x1
    unsigned long long Up[13];        // pairs over h; Up[12] = (U[24], 0)
    float bg = 0.f;
    if (tid < G4) {
#pragma unroll
        for (int i = 0; i < CHh / 2; i++)
            Wp[i] = pk2(Wl[(2 * i) * G4 + tid], Wl[(2 * i + 1) * G4 + tid]);
#pragma unroll
        for (int i = 0; i < 12; i++)
            Up[i] = pk2(Ul[(2 * i) * G4 + tid], Ul[(2 * i + 1) * G4 + tid]);
        Up[12] = pk2(Ul[24 * G4 + tid], 0.f);
        bg = bl[tid];
    }
    float wc0 = 0.f, wc1 = 0.f, wc2 = 0.f, bcv = 0.f;
    if (tid < CHh) {
        wc0 = Wc[0 * CHh + tid];
        wc1 = Wc[1 * CHh + tid];
        wc2 = Wc[2 * CHh + tid];
        bcv = bc[tid];
    }
    float cst = 0.f;                 // cell state (tid < 25)
    if (tid < 28) hs[tid] = 0.f;
    __syncthreads();                 // xsm / hs ready

    float* hout = g_h + ((long long)n * Tt * Vv + v) * FFf;

#pragma unroll 1
    for (int t = 0; t < Tt; t++) {
        // ---- phase 1: x1 row (64 ch) from 1x1 conv, x from smem ----
        if (tid < CHh) {
            float a = fmaf(xsm[t * 3 + 0], wc0, bcv);
            a = fmaf(xsm[t * 3 + 1], wc1, a);
            a = fmaf(xsm[t * 3 + 2], wc2, a);
            x1s[tid] = fmaxf(a, 0.f);
        }
        __syncthreads();  // x1s ready; also orders prev phase3 hs/zs

        // ---- phase 2: gate pre-activation z[tid], split f32x2 accumulators ----
        if (tid < G4) {
            const ulonglong2* xx = (const ulonglong2*)x1s;
            const ulonglong2* hh = (const ulonglong2*)hs;
            unsigned long long a0 = pk2(bg, 0.f), a1 = 0, a2 = 0, a3 = 0;
#pragma unroll
            for (int i = 0; i < 16; i++) {
                ulonglong2 p = xx[i];
                if ((i & 1) == 0) { a0 = ffma2(p.x, Wp[2 * i], a0); a1 = ffma2(p.y, Wp[2 * i + 1], a1); }
                else              { a2 = ffma2(p.x, Wp[2 * i], a2); a3 = ffma2(p.y, Wp[2 * i + 1], a3); }
            }
#pragma unroll
            for (int i = 0; i < 7; i++) {
                ulonglong2 p = hh[i];
                if ((i & 1) == 0) { a0 = ffma2(p.x, Up[2 * i], a0); if (i < 6) a1 = ffma2(p.y, Up[2 * i + 1], a1); }
                else              { a2 = ffma2(p.x, Up[2 * i], a2); a3 = ffma2(p.y, Up[2 * i + 1], a3); }
            }
            unsigned long long s01 = add2(a0, a1), s23 = add2(a2, a3);
            unsigned long long sall = add2(s01, s23);
            float lo, hi; upk2(sall, lo, hi);
            zs[tid] = lo + hi;
        }
        __syncthreads();  // zs ready

        // ---- phase 3: gates, state update, store h (no softmax here) ----
        if (tid < FFf) {
            float zi = zs[tid];
            float zf = zs[tid + 25];
            float zg = zs[tid + 50];
            float zo = zs[tid + 75];
            cst = hsig(zf) * cst + hsig(zi) * tanh_acc(zg);
            float h = hsig(zo) * tanh_acc(cst);
            hs[tid] = h;
            hout[(long long)t * Vv * FFf + tid] = h;
        }
        // next iteration's first __syncthreads orders hs/zs
    }
}

// One block per (n,t): leaky+bias+softmax of h rows (25x25), recompute x1
// (25x64), out = coefs @ x1.
__global__ __launch_bounds__(256) void agg_kernel(
    const float* __restrict__ x,
    const float* __restrict__ Wc,
    const float* __restrict__ bc,
    const float* __restrict__ bias,  // (25,25)
    float* __restrict__ out)
{
    const int nt = blockIdx.x;
    const int tid = threadIdx.x;

    __shared__ float asm_[Vv][33];                 // pre-softmax then coefs
    __shared__ __align__(16) float x1s[Vv][CHh];   // 6.4KB
    __shared__ float xs[XST];

    // load h, apply leaky_relu + bias
    const float* hrow = g_h + (long long)nt * Vv * FFf;
    for (int i = tid; i < Vv * FFf; i += 256) {
        int vv = i / 25, f = i - vv * 25;
        float hv = hrow[i];
        asm_[vv][f] = (hv > 0.f ? hv : 0.2f * hv) + bias[vv * Vv + f];
    }
    if (tid < XST) xs[tid] = x[(long long)nt * XST + tid];
    __syncthreads();

    // x1 tile
    for (int i = tid; i < Vv * CHh; i += 256) {
        int w = i >> 6, d = i & 63;
        float a = fmaf(xs[w * 3 + 0], Wc[0 * CHh + d], bc[d]);
        a = fmaf(xs[w * 3 + 1], Wc[1 * CHh + d], a);
        a = fmaf(xs[w * 3 + 2], Wc[2 * CHh + d], a);
        x1s[w][d] = fmaxf(a, 0.f);
    }

    // softmax per row: warp per row, rows strided by 8
    {
        int wrp = tid >> 5, lane = tid & 31;
        for (int r = wrp; r < Vv; r += 8) {
            float a = (lane < FFf) ? asm_[r][lane] : -1e30f;
            float m = a;
#pragma unroll
            for (int off = 16; off >= 1; off >>= 1)
                m = fmaxf(m, __shfl_xor_sync(0xffffffffu, m, off));
            float e = (lane < FFf) ? __expf(a - m) : 0.f;
            float s = e;
#pragma unroll
            for (int off = 16; off >= 1; off >>= 1)
                s += __shfl_xor_sync(0xffffffffu, s, off);
            if (lane < FFf) asm_[r][lane] = e / s;
        }
    }
    __syncthreads();

    // aggregate: threads 0..199, thread = (v, d4); outputs at d4 and d4+8
    if (tid < 200) {
        int vv = tid >> 3, d4 = tid & 7;
        float4 A = make_float4(0.f, 0.f, 0.f, 0.f);
        float4 B = A;
#pragma unroll 5
        for (int w = 0; w < Vv; w++) {
            float cf = asm_[vv][w];
            float4 xa = ((const float4*)x1s[w])[d4];
            float4 xb = ((const float4*)x1s[w])[d4 + 8];
            A.x = fmaf(cf, xa.x, A.x); A.y = fmaf(cf, xa.y, A.y);
            A.z = fmaf(cf, xa.z, A.z); A.w = fmaf(cf, xa.w, A.w);
            B.x = fmaf(cf, xb.x, B.x); B.y = fmaf(cf, xb.y, B.y);
            B.z = fmaf(cf, xb.z, B.z); B.w = fmaf(cf, xb.w, B.w);
        }
        float4* oblk = (float4*)(out + (long long)nt * Vv * CHh);
        oblk[vv * 16 + d4] = A;
        oblk[vv * 16 + d4 + 8] = B;
    }
}

extern "C" void kernel_launch(void* const* d_in, const int* in_sizes, int n_in,
                              void* d_out, int out_size)
{
    const float* x    = (const float*)d_in[0];
    const float* Wc   = (const float*)d_in[1];
    const float* bc   = (const float*)d_in[2];
    const float* Wl   = (const float*)d_in[3];
    const float* Ul   = (const float*)d_in[4];
    const float* bl   = (const float*)d_in[5];
    const float* bias = (const float*)d_in[6];
    float* out = (float*)d_out;

    scan_kernel<<<Nn * Vv, 128>>>(x, Wc, bc, Wl, Ul, bl);
    agg_kernel<<<Nn * Tt, 256>>>(x, Wc, bc, bias, out);
}